// round 13
// baseline (speedup 1.0000x reference)
#include <cuda_runtime.h>
#include <cuda_bf16.h>
#include <math.h>

// ---------------------------------------------------------------------------
// GaussianSplattingDecoder.
// occ[v,c] = sum_g exp(-0.5*mahal)*opacity_g*sem_g[c] (dist^2 < R^2) + empty
// V = 100*100*8, N = 2048, C = 17.
// R12: launch_bounds(256,4) -> 64-reg budget for deeper unroll pipelining
// (grid is 4.2 CTAs/SM anyway, 5th slot was dead); -0.5 folded into prepped
// covariances (shorter exp dependency chain); pointer-increment inner loop.
// Base: R11 (FFMA2 accumulate, coalesced output, branchless loop, packed
// means cull, chunked smem staging).
// ---------------------------------------------------------------------------

#define N_GAUSS 2048
#define NUM_CLASSES 17
#define PROP_STRIDE 28      // 11 + 17
#define RADIUS_SQ 16.0f
#define CULL_MARGIN 0.01f
#define STAGE_CAP 256

// Packed means for culling: 32 KB, contiguous, L2-resident.
__device__ float4 g_means[N_GAUSS];

// Preprocessed gaussians: 7 float4s each (224 KB, L2-resident).
// Covariance entries pre-scaled so that e = sum(...) is ALREADY -0.5*mahal:
// f4[0] = {mx, my, mz, h00}          h00 = -0.5*c00
// f4[1] = {h01, h02, h11, h12}       h01 = -c01, h02 = -c02, h11 = -0.5*c11, h12 = -c12
// f4[2] = {h22, s16, s0, s1}         h22 = -0.5*c22, s = opacity * semantics
// f4[3] = {s2, s3, s4, s5}
// f4[4] = {s6, s7, s8, s9}
// f4[5] = {s10, s11, s12, s13}
// f4[6] = {s14, s15, 0, 0}
__device__ float4 g_prep[N_GAUSS * 7];

#define FMA2(accp, pair, ww) \
    asm("fma.rn.f32x2 %0, %1, %2, %0;" : "+l"(accp) : "l"(pair), "l"(ww))
#define PACK2(dst, lo, hi) \
    asm("mov.b64 %0, {%1, %2};" : "=l"(dst) : "f"(lo), "f"(hi))
#define UNPACK2(lo, hi, src) \
    asm("mov.b64 {%0, %1}, %2;" : "=f"(lo), "=f"(hi) : "l"(src))

__device__ __forceinline__ float softplus_stable(float x) {
    return fmaxf(x, 0.0f) + log1pf(expf(-fabsf(x)));
}

__global__ void prep_kernel(const float* __restrict__ props) {
    int g = blockIdx.x * blockDim.x + threadIdx.x;
    if (g >= N_GAUSS) return;
    const float* p = props + g * PROP_STRIDE;

    float s0 = fmaxf(softplus_stable(p[3]), 1e-4f);
    float s1 = fmaxf(softplus_stable(p[4]), 1e-4f);
    float s2 = fmaxf(softplus_stable(p[5]), 1e-4f);
    float a0 = 1.0f / fmaxf(s0 * s0, 1e-8f);
    float a1 = 1.0f / fmaxf(s1 * s1, 1e-8f);
    float a2 = 1.0f / fmaxf(s2 * s2, 1e-8f);

    float qw = p[6], qx = p[7], qy = p[8], qz = p[9];
    float inv_n = 1.0f / fmaxf(sqrtf(qw * qw + qx * qx + qy * qy + qz * qz), 1e-8f);
    qw *= inv_n; qx *= inv_n; qy *= inv_n; qz *= inv_n;

    float R00 = 1.0f - 2.0f * (qy * qy + qz * qz);
    float R01 = 2.0f * (qx * qy - qw * qz);
    float R02 = 2.0f * (qx * qz + qw * qy);
    float R10 = 2.0f * (qx * qy + qw * qz);
    float R11 = 1.0f - 2.0f * (qx * qx + qz * qz);
    float R12 = 2.0f * (qy * qz - qw * qx);
    float R20 = 2.0f * (qx * qz - qw * qy);
    float R21 = 2.0f * (qy * qz + qw * qx);
    float R22 = 1.0f - 2.0f * (qx * qx + qy * qy);

    float c00 = a0 * R00 * R00 + a1 * R01 * R01 + a2 * R02 * R02;
    float c01 = a0 * R00 * R10 + a1 * R01 * R11 + a2 * R02 * R12;
    float c02 = a0 * R00 * R20 + a1 * R01 * R21 + a2 * R02 * R22;
    float c11 = a0 * R10 * R10 + a1 * R11 * R11 + a2 * R12 * R12;
    float c12 = a0 * R10 * R20 + a1 * R11 * R21 + a2 * R12 * R22;
    float c22 = a0 * R20 * R20 + a1 * R21 * R21 + a2 * R22 * R22;

    float op = 1.0f / (1.0f + expf(-p[10]));

    g_means[g] = make_float4(p[0], p[1], p[2], 0.0f);

    float4* o = g_prep + g * 7;
    o[0] = make_float4(p[0], p[1], p[2], -0.5f * c00);
    o[1] = make_float4(-c01, -c02, -0.5f * c11, -c12);
    o[2] = make_float4(-0.5f * c22, op * p[27], op * p[11], op * p[12]);
    o[3] = make_float4(op * p[13], op * p[14], op * p[15], op * p[16]);
    o[4] = make_float4(op * p[17], op * p[18], op * p[19], op * p[20]);
    o[5] = make_float4(op * p[21], op * p[22], op * p[23], op * p[24]);
    o[6] = make_float4(op * p[25], op * p[26], 0.0f, 0.0f);
}

// Tile = 4x4x8 voxels. 256 threads: tid&127 -> voxel, tid>>7 -> list half.
__global__ __launch_bounds__(256, 4) void splat_kernel(
    const float* __restrict__ vox_coords, float* __restrict__ out)
{
    const int tid = threadIdx.x;
    const int tx = blockIdx.x * 4;
    const int ty = blockIdx.y * 4;
    const int vtid = tid & 127;
    const int half = tid >> 7;
    const int lx = vtid >> 5;          // 0..3
    const int ly = (vtid >> 3) & 3;    // 0..3
    const int lz = vtid & 7;           // 0..7
    const int v = ((tx + lx) * 100 + (ty + ly)) * 8 + lz;

    const float px = vox_coords[v * 3 + 0];
    const float py = vox_coords[v * 3 + 1];
    const float pz = vox_coords[v * 3 + 2];

    const float dxy = 80.0f / 99.0f;
    const float bx0 = -40.0f + tx * dxy - CULL_MARGIN;
    const float bx1 = -40.0f + (tx + 3) * dxy + CULL_MARGIN;
    const float by0 = -40.0f + ty * dxy - CULL_MARGIN;
    const float by1 = -40.0f + (ty + 3) * dxy + CULL_MARGIN;
    const float bz0 = -1.0f - CULL_MARGIN;
    const float bz1 = 5.4f + CULL_MARGIN;

    __shared__ unsigned short s_list[N_GAUSS];   // 4 KB
    __shared__ float4 s_stage[STAGE_CAP * 7];    // 28 KB; aliased for output
    __shared__ int s_warp_sums[8];

    // --- Phase 1: AABB cull on packed means (32 KB contiguous) ---
    const int gbase = tid * 8;
    unsigned int hitmask = 0;
#pragma unroll
    for (int i = 0; i < 8; i++) {
        const float4 p0 = __ldg(g_means + gbase + i);
        float ex = fmaxf(fmaxf(bx0 - p0.x, p0.x - bx1), 0.0f);
        float ey = fmaxf(fmaxf(by0 - p0.y, p0.y - by1), 0.0f);
        float ez = fmaxf(fmaxf(bz0 - p0.z, p0.z - bz1), 0.0f);
        if (ex * ex + ey * ey + ez * ez < RADIUS_SQ) hitmask |= (1u << i);
    }
    int cnt = __popc(hitmask);

    // Deterministic order-preserving compaction
    const int lane = tid & 31, wid = tid >> 5;
    int incl = cnt;
#pragma unroll
    for (int o = 1; o < 32; o <<= 1) {
        int vsh = __shfl_up_sync(0xffffffffu, incl, o);
        if (lane >= o) incl += vsh;
    }
    if (lane == 31) s_warp_sums[wid] = incl;
    __syncthreads();
    int woff = 0, total = 0;
#pragma unroll
    for (int w = 0; w < 8; w++) {
        int ws = s_warp_sums[w];
        if (w < wid) woff += ws;
        total += ws;
    }
    int offset = woff + incl - cnt;
    unsigned int m = hitmask;
    while (m) {
        int i = __ffs(m) - 1;
        m &= m - 1;
        s_list[offset++] = (unsigned short)(gbase + i);
    }
    __syncthreads();

    // --- Phase 2/3 chunked: stage survivors, accumulate (branchless, f32x2) --
    unsigned long long accp[8];
#pragma unroll
    for (int i = 0; i < 8; i++) accp[i] = 0ull;   // == (0.0f, 0.0f)
    float acc16 = 0.0f;

    for (int base = 0; base < total; base += STAGE_CAP) {
        const int nc = min(STAGE_CAP, total - base);

        // cooperative copy: 7 float4s per survivor, spread across threads
        for (int t = tid; t < nc * 7; t += 256) {
            const int k = t / 7, j = t - k * 7;
            s_stage[k * 7 + j] = __ldg(g_prep + (int)s_list[base + k] * 7 + j);
        }
        __syncthreads();

        const int mid = nc >> 1;
        const int k0 = half ? mid : 0;
        const int k1 = half ? nc : mid;

        const float4* P = s_stage + k0 * 7;
#pragma unroll 4
        for (int k = k0; k < k1; k++, P += 7) {
            const ulonglong2* Q = (const ulonglong2*)P;
            const float4 p0 = P[0];
            const float4 p1 = P[1];
            const ulonglong2 q2 = Q[2];     // (h22,s16) (s0,s1)
            float h22, s16;
            UNPACK2(h22, s16, q2.x);

            const float d0 = px - p0.x;
            const float d1 = py - p0.y;
            const float d2 = pz - p0.z;
            const bool inside = (d0 * d0 + d1 * d1 + d2 * d2) < RADIUS_SQ;
            // e = -0.5 * mahal (scaling folded into prepped entries)
            float t0 = p0.w * d0;                 // h00*d0
            t0 = fmaf(p1.x, d1, t0);              // + h01*d1
            t0 = fmaf(p1.y, d2, t0);              // + h02*d2
            float t1 = p1.z * d1;                 // h11*d1
            t1 = fmaf(p1.w, d2, t1);              // + h12*d2
            float e = t0 * d0;
            e = fmaf(t1, d1, e);
            e = fmaf(h22 * d2, d2, e);
            float w = inside ? __expf(e) : 0.0f;
            unsigned long long ww;
            PACK2(ww, w, w);

            FMA2(accp[0], q2.y, ww);
            {
                const ulonglong2 q = Q[3];
                FMA2(accp[1], q.x, ww);
                FMA2(accp[2], q.y, ww);
            }
            {
                const ulonglong2 q = Q[4];
                FMA2(accp[3], q.x, ww);
                FMA2(accp[4], q.y, ww);
            }
            {
                const ulonglong2 q = Q[5];
                FMA2(accp[5], q.x, ww);
                FMA2(accp[6], q.y, ww);
            }
            FMA2(accp[7], Q[6].x, ww);
            acc16 = fmaf(w, s16, acc16);
        }
        __syncthreads();   // before next chunk overwrites s_stage
    }

    // Unpack accumulators: classes 0..15 from pairs, 16 scalar.
    float acc[NUM_CLASSES];
#pragma unroll
    for (int i = 0; i < 8; i++) UNPACK2(acc[2 * i], acc[2 * i + 1], accp[i]);
    acc[16] = acc16;

    // --- Combine halves + coalesced output via smem transpose ---
    float* s_out = (float*)s_stage;
    float* s_part = s_out + 128 * NUM_CLASSES;

    if (half) {
#pragma unroll
        for (int c = 0; c < NUM_CLASSES; c++)
            s_part[vtid * NUM_CLASSES + c] = acc[c];
    }
    __syncthreads();
    if (!half) {
#pragma unroll
        for (int c = 0; c < NUM_CLASSES; c++)
            acc[c] += s_part[vtid * NUM_CLASSES + c];

        // Empty term: center=(0,0,2.2), inv=(1/1600,1/1600,1/10.24)
        const float de2 = pz - 2.2f;
        const float me = px * px * (1.0f / 1600.0f)
                       + py * py * (1.0f / 1600.0f)
                       + de2 * de2 * (1.0f / 10.24f);
        acc[0] += 0.1f * __expf(-0.5f * me) * 5.0f;

#pragma unroll
        for (int c = 0; c < NUM_CLASSES; c++)
            s_out[vtid * NUM_CLASSES + c] = acc[c];
    }
    __syncthreads();

    // Cooperative coalesced store: for fixed lx, 544 contiguous gmem floats.
    {
        const float4* s4 = (const float4*)s_out;
        for (int t4 = tid; t4 < 544; t4 += 256) {
            const int lxb = t4 / 136;
            const int j4 = t4 - lxb * 136;
            float4* dst = (float4*)(out + ((size_t)((tx + lxb) * 100 + ty) * 8) * NUM_CLASSES);
            dst[j4] = s4[lxb * 136 + j4];
        }
    }
}

extern "C" void kernel_launch(void* const* d_in, const int* in_sizes, int n_in,
                              void* d_out, int out_size) {
    const float* props = (const float*)d_in[0];
    const float* vox   = (const float*)d_in[1];
    if (n_in >= 2 && in_sizes[0] == 100 * 100 * 8 * 3 &&
        in_sizes[1] == N_GAUSS * PROP_STRIDE) {
        const float* t = props; props = vox; vox = t;
    }
    float* out = (float*)d_out;

    prep_kernel<<<64, 32>>>(props);
    splat_kernel<<<dim3(25, 25), 256>>>(vox, out);
}

// round 16
// speedup vs baseline: 1.0175x; 1.0175x over previous
#include <cuda_runtime.h>
#include <cuda_bf16.h>
#include <math.h>

// ---------------------------------------------------------------------------
// GaussianSplattingDecoder.
// occ[v,c] = sum_g exp(-0.5*mahal)*opacity_g*sem_g[c] (dist^2 < R^2) + empty
// V = 100*100*8, N = 2048, C = 17.
// R14 (= R13 resubmit; infra failure): revert R12's (256,4) [592 slots < 625
// CTAs -> 2nd wave]. Back to (256,5) single wave. Folded exponent constants
// (-0.5*log2e into covariances) + raw ex2.approx + pointer-increment loop.
// Base: R11 (FFMA2 accumulate, coalesced output, branchless loop, packed
// means cull, chunked smem staging).
// ---------------------------------------------------------------------------

#define N_GAUSS 2048
#define NUM_CLASSES 17
#define PROP_STRIDE 28      // 11 + 17
#define RADIUS_SQ 16.0f
#define CULL_MARGIN 0.01f
#define STAGE_CAP 256
#define NEG_HALF_LOG2E (-0.72134752044448170368f)   // -0.5 * log2(e)
#define NEG_LOG2E      (-1.44269504088896340736f)   // -log2(e)

// Packed means for culling: 32 KB, contiguous, L2-resident.
__device__ float4 g_means[N_GAUSS];

// Preprocessed gaussians: 7 float4s each (224 KB, L2-resident).
// Covariance entries pre-scaled so e = quadform is ALREADY -0.5*log2e*mahal:
// f4[0] = {mx, my, mz, h00}          h00 = -0.5*log2e*c00
// f4[1] = {h01, h02, h11, h12}       h01 = -log2e*c01, h02 = -log2e*c02,
//                                    h11 = -0.5*log2e*c11, h12 = -log2e*c12
// f4[2] = {h22, s16, s0, s1}         h22 = -0.5*log2e*c22, s = opacity*sem
// f4[3] = {s2, s3, s4, s5}
// f4[4] = {s6, s7, s8, s9}
// f4[5] = {s10, s11, s12, s13}
// f4[6] = {s14, s15, 0, 0}
__device__ float4 g_prep[N_GAUSS * 7];

#define FMA2(accp, pair, ww) \
    asm("fma.rn.f32x2 %0, %1, %2, %0;" : "+l"(accp) : "l"(pair), "l"(ww))
#define PACK2(dst, lo, hi) \
    asm("mov.b64 %0, {%1, %2};" : "=l"(dst) : "f"(lo), "f"(hi))
#define UNPACK2(lo, hi, src) \
    asm("mov.b64 {%0, %1}, %2;" : "=f"(lo), "=f"(hi) : "l"(src))
#define EX2(dst, src) \
    asm("ex2.approx.f32 %0, %1;" : "=f"(dst) : "f"(src))

__device__ __forceinline__ float softplus_stable(float x) {
    return fmaxf(x, 0.0f) + log1pf(expf(-fabsf(x)));
}

__global__ void prep_kernel(const float* __restrict__ props) {
    int g = blockIdx.x * blockDim.x + threadIdx.x;
    if (g >= N_GAUSS) return;
    const float* p = props + g * PROP_STRIDE;

    float s0 = fmaxf(softplus_stable(p[3]), 1e-4f);
    float s1 = fmaxf(softplus_stable(p[4]), 1e-4f);
    float s2 = fmaxf(softplus_stable(p[5]), 1e-4f);
    float a0 = 1.0f / fmaxf(s0 * s0, 1e-8f);
    float a1 = 1.0f / fmaxf(s1 * s1, 1e-8f);
    float a2 = 1.0f / fmaxf(s2 * s2, 1e-8f);

    float qw = p[6], qx = p[7], qy = p[8], qz = p[9];
    float inv_n = 1.0f / fmaxf(sqrtf(qw * qw + qx * qx + qy * qy + qz * qz), 1e-8f);
    qw *= inv_n; qx *= inv_n; qy *= inv_n; qz *= inv_n;

    float R00 = 1.0f - 2.0f * (qy * qy + qz * qz);
    float R01 = 2.0f * (qx * qy - qw * qz);
    float R02 = 2.0f * (qx * qz + qw * qy);
    float R10 = 2.0f * (qx * qy + qw * qz);
    float R11 = 1.0f - 2.0f * (qx * qx + qz * qz);
    float R12 = 2.0f * (qy * qz - qw * qx);
    float R20 = 2.0f * (qx * qz - qw * qy);
    float R21 = 2.0f * (qy * qz + qw * qx);
    float R22 = 1.0f - 2.0f * (qx * qx + qy * qy);

    float c00 = a0 * R00 * R00 + a1 * R01 * R01 + a2 * R02 * R02;
    float c01 = a0 * R00 * R10 + a1 * R01 * R11 + a2 * R02 * R12;
    float c02 = a0 * R00 * R20 + a1 * R01 * R21 + a2 * R02 * R22;
    float c11 = a0 * R10 * R10 + a1 * R11 * R11 + a2 * R12 * R12;
    float c12 = a0 * R10 * R20 + a1 * R11 * R21 + a2 * R12 * R22;
    float c22 = a0 * R20 * R20 + a1 * R21 * R21 + a2 * R22 * R22;

    float op = 1.0f / (1.0f + expf(-p[10]));

    g_means[g] = make_float4(p[0], p[1], p[2], 0.0f);

    float4* o = g_prep + g * 7;
    o[0] = make_float4(p[0], p[1], p[2], NEG_HALF_LOG2E * c00);
    o[1] = make_float4(NEG_LOG2E * c01, NEG_LOG2E * c02,
                       NEG_HALF_LOG2E * c11, NEG_LOG2E * c12);
    o[2] = make_float4(NEG_HALF_LOG2E * c22, op * p[27], op * p[11], op * p[12]);
    o[3] = make_float4(op * p[13], op * p[14], op * p[15], op * p[16]);
    o[4] = make_float4(op * p[17], op * p[18], op * p[19], op * p[20]);
    o[5] = make_float4(op * p[21], op * p[22], op * p[23], op * p[24]);
    o[6] = make_float4(op * p[25], op * p[26], 0.0f, 0.0f);
}

// Tile = 4x4x8 voxels. 256 threads: tid&127 -> voxel, tid>>7 -> list half.
__global__ __launch_bounds__(256, 5) void splat_kernel(
    const float* __restrict__ vox_coords, float* __restrict__ out)
{
    const int tid = threadIdx.x;
    const int tx = blockIdx.x * 4;
    const int ty = blockIdx.y * 4;
    const int vtid = tid & 127;
    const int half = tid >> 7;
    const int lx = vtid >> 5;          // 0..3
    const int ly = (vtid >> 3) & 3;    // 0..3
    const int lz = vtid & 7;           // 0..7
    const int v = ((tx + lx) * 100 + (ty + ly)) * 8 + lz;

    const float px = vox_coords[v * 3 + 0];
    const float py = vox_coords[v * 3 + 1];
    const float pz = vox_coords[v * 3 + 2];

    const float dxy = 80.0f / 99.0f;
    const float bx0 = -40.0f + tx * dxy - CULL_MARGIN;
    const float bx1 = -40.0f + (tx + 3) * dxy + CULL_MARGIN;
    const float by0 = -40.0f + ty * dxy - CULL_MARGIN;
    const float by1 = -40.0f + (ty + 3) * dxy + CULL_MARGIN;
    const float bz0 = -1.0f - CULL_MARGIN;
    const float bz1 = 5.4f + CULL_MARGIN;

    __shared__ unsigned short s_list[N_GAUSS];   // 4 KB
    __shared__ float4 s_stage[STAGE_CAP * 7];    // 28 KB; aliased for output
    __shared__ int s_warp_sums[8];

    // --- Phase 1: AABB cull on packed means (32 KB contiguous) ---
    const int gbase = tid * 8;
    unsigned int hitmask = 0;
#pragma unroll
    for (int i = 0; i < 8; i++) {
        const float4 p0 = __ldg(g_means + gbase + i);
        float ex = fmaxf(fmaxf(bx0 - p0.x, p0.x - bx1), 0.0f);
        float ey = fmaxf(fmaxf(by0 - p0.y, p0.y - by1), 0.0f);
        float ez = fmaxf(fmaxf(bz0 - p0.z, p0.z - bz1), 0.0f);
        if (ex * ex + ey * ey + ez * ez < RADIUS_SQ) hitmask |= (1u << i);
    }
    int cnt = __popc(hitmask);

    // Deterministic order-preserving compaction
    const int lane = tid & 31, wid = tid >> 5;
    int incl = cnt;
#pragma unroll
    for (int o = 1; o < 32; o <<= 1) {
        int vsh = __shfl_up_sync(0xffffffffu, incl, o);
        if (lane >= o) incl += vsh;
    }
    if (lane == 31) s_warp_sums[wid] = incl;
    __syncthreads();
    int woff = 0, total = 0;
#pragma unroll
    for (int w = 0; w < 8; w++) {
        int ws = s_warp_sums[w];
        if (w < wid) woff += ws;
        total += ws;
    }
    int offset = woff + incl - cnt;
    unsigned int m = hitmask;
    while (m) {
        int i = __ffs(m) - 1;
        m &= m - 1;
        s_list[offset++] = (unsigned short)(gbase + i);
    }
    __syncthreads();

    // --- Phase 2/3 chunked: stage survivors, accumulate (branchless, f32x2) --
    unsigned long long accp[8];
#pragma unroll
    for (int i = 0; i < 8; i++) accp[i] = 0ull;   // == (0.0f, 0.0f)
    float acc16 = 0.0f;

    for (int base = 0; base < total; base += STAGE_CAP) {
        const int nc = min(STAGE_CAP, total - base);

        // cooperative copy: 7 float4s per survivor, spread across threads
        for (int t = tid; t < nc * 7; t += 256) {
            const int k = t / 7, j = t - k * 7;
            s_stage[k * 7 + j] = __ldg(g_prep + (int)s_list[base + k] * 7 + j);
        }
        __syncthreads();

        const int mid = nc >> 1;
        const int k0 = half ? mid : 0;
        const int k1 = half ? nc : mid;

        const float4* P = s_stage + k0 * 7;
#pragma unroll 4
        for (int k = k0; k < k1; k++, P += 7) {
            const ulonglong2* Q = (const ulonglong2*)P;
            const float4 p0 = P[0];
            const float4 p1 = P[1];
            const ulonglong2 q2 = Q[2];     // (h22,s16) (s0,s1)
            float h22, s16;
            UNPACK2(h22, s16, q2.x);

            const float d0 = px - p0.x;
            const float d1 = py - p0.y;
            const float d2 = pz - p0.z;
            const bool inside = (d0 * d0 + d1 * d1 + d2 * d2) < RADIUS_SQ;
            // e = -0.5*log2e*mahal (all scaling folded into prepped entries)
            float t0 = p0.w * d0;
            t0 = fmaf(p1.x, d1, t0);
            t0 = fmaf(p1.y, d2, t0);
            float t1 = p1.z * d1;
            t1 = fmaf(p1.w, d2, t1);
            float e = t0 * d0;
            e = fmaf(t1, d1, e);
            e = fmaf(h22 * d2, d2, e);
            float wexp;
            EX2(wexp, e);
            float w = inside ? wexp : 0.0f;
            unsigned long long ww;
            PACK2(ww, w, w);

            FMA2(accp[0], q2.y, ww);
            {
                const ulonglong2 q = Q[3];
                FMA2(accp[1], q.x, ww);
                FMA2(accp[2], q.y, ww);
            }
            {
                const ulonglong2 q = Q[4];
                FMA2(accp[3], q.x, ww);
                FMA2(accp[4], q.y, ww);
            }
            {
                const ulonglong2 q = Q[5];
                FMA2(accp[5], q.x, ww);
                FMA2(accp[6], q.y, ww);
            }
            FMA2(accp[7], Q[6].x, ww);
            acc16 = fmaf(w, s16, acc16);
        }
        __syncthreads();   // before next chunk overwrites s_stage
    }

    // Unpack accumulators: classes 0..15 from pairs, 16 scalar.
    float acc[NUM_CLASSES];
#pragma unroll
    for (int i = 0; i < 8; i++) UNPACK2(acc[2 * i], acc[2 * i + 1], accp[i]);
    acc[16] = acc16;

    // --- Combine halves + coalesced output via smem transpose ---
    float* s_out = (float*)s_stage;
    float* s_part = s_out + 128 * NUM_CLASSES;

    if (half) {
#pragma unroll
        for (int c = 0; c < NUM_CLASSES; c++)
            s_part[vtid * NUM_CLASSES + c] = acc[c];
    }
    __syncthreads();
    if (!half) {
#pragma unroll
        for (int c = 0; c < NUM_CLASSES; c++)
            acc[c] += s_part[vtid * NUM_CLASSES + c];

        // Empty term: center=(0,0,2.2), inv=(1/1600,1/1600,1/10.24)
        const float de2 = pz - 2.2f;
        const float me = px * px * (1.0f / 1600.0f)
                       + py * py * (1.0f / 1600.0f)
                       + de2 * de2 * (1.0f / 10.24f);
        acc[0] += 0.1f * __expf(-0.5f * me) * 5.0f;

#pragma unroll
        for (int c = 0; c < NUM_CLASSES; c++)
            s_out[vtid * NUM_CLASSES + c] = acc[c];
    }
    __syncthreads();

    // Cooperative coalesced store: for fixed lx, 544 contiguous gmem floats.
    {
        const float4* s4 = (const float4*)s_out;
        for (int t4 = tid; t4 < 544; t4 += 256) {
            const int lxb = t4 / 136;
            const int j4 = t4 - lxb * 136;
            float4* dst = (float4*)(out + ((size_t)((tx + lxb) * 100 + ty) * 8) * NUM_CLASSES);
            dst[j4] = s4[lxb * 136 + j4];
        }
    }
}

extern "C" void kernel_launch(void* const* d_in, const int* in_sizes, int n_in,
                              void* d_out, int out_size) {
    const float* props = (const float*)d_in[0];
    const float* vox   = (const float*)d_in[1];
    if (n_in >= 2 && in_sizes[0] == 100 * 100 * 8 * 3 &&
        in_sizes[1] == N_GAUSS * PROP_STRIDE) {
        const float* t = props; props = vox; vox = t;
    }
    float* out = (float*)d_out;

    prep_kernel<<<64, 32>>>(props);
    splat_kernel<<<dim3(25, 25), 256>>>(vox, out);
}